// round 14
// baseline (speedup 1.0000x reference)
#include <cuda_runtime.h>
#include <cuda_fp16.h>
#include <math.h>
#include <stdint.h>

#define NT 4096      // tokens = B*S
#define ND 1024      // hidden
#define NH 512       // intermediate
#define NE 8         // experts

// ---- device scratch (static; no allocations allowed) ----
__device__ int    g_cnt[NE];          // zero-init at load; re-zeroed by combine_kernel each call
__device__ int    g_tokslot[NE * NT];
__device__ float  g_gate[NE * NT];
__device__ __half g_x16[(size_t)NT * ND];
__device__ __half g_wout16[(size_t)NE * ND * NH];
__device__ __half g_h16[(size_t)NE * NT * NH];
__device__ float  g_y[(size_t)NT * 2 * ND];
__device__ float  g_logits_scratch[(size_t)NT * NE];

// ======================= helpers =======================
__device__ __forceinline__ uint32_t smem_u32(const void* p) {
    uint32_t a;
    asm("{ .reg .u64 t; cvta.to.shared.u64 t, %1; cvt.u32.u64 %0, t; }" : "=r"(a) : "l"(p));
    return a;
}
#define CPA16(dst, src) asm volatile("cp.async.cg.shared.global [%0], [%1], 16;" :: "r"(dst), "l"(src))
#define CPCOMMIT()      asm volatile("cp.async.commit_group;")
#define CPWAIT(n)       asm volatile("cp.async.wait_group %0;" :: "n"(n))
#define LDM_X4(r0, r1, r2, r3, addr) \
    asm volatile("ldmatrix.sync.aligned.m8n8.x4.shared.b16 {%0,%1,%2,%3}, [%4];" \
        : "=r"(r0), "=r"(r1), "=r"(r2), "=r"(r3) : "r"(addr))
#define MMA16(d, a, b0, b1) \
    asm volatile("mma.sync.aligned.m16n8k16.row.col.f32.f16.f16.f32 " \
        "{%0,%1,%2,%3}, {%4,%5,%6,%7}, {%8,%9}, {%0,%1,%2,%3};" \
        : "+f"((d)[0]), "+f"((d)[1]), "+f"((d)[2]), "+f"((d)[3]) \
        : "r"((a)[0]), "r"((a)[1]), "r"((a)[2]), "r"((a)[3]), "r"(b0), "r"(b1))

// load 8 consecutive fp32, convert to 8 fp16 packed in uint4
__device__ __forceinline__ uint4 ldgcvt8(const float* p) {
    float4 f0 = *reinterpret_cast<const float4*>(p);
    float4 f1 = *reinterpret_cast<const float4*>(p + 4);
    __half2 h0 = __floats2half2_rn(f0.x, f0.y);
    __half2 h1 = __floats2half2_rn(f0.z, f0.w);
    __half2 h2 = __floats2half2_rn(f1.x, f1.y);
    __half2 h3 = __floats2half2_rn(f1.z, f1.w);
    uint4 v;
    v.x = *reinterpret_cast<uint32_t*>(&h0);
    v.y = *reinterpret_cast<uint32_t*>(&h1);
    v.z = *reinterpret_cast<uint32_t*>(&h2);
    v.w = *reinterpret_cast<uint32_t*>(&h3);
    return v;
}

// =====================================================================
// prep_kernel: blocks [0, NT) = router (+x fp16 convert);
//              blocks [NT, NT + CVTO_BLOCKS) = w_out fp32->fp16 convert.
// (w_in is consumed fp32 directly by ffn1 — no materialized fp16 copy.)
#define NWO4 (NE * ND * NH / 4)          // 1048576 float4
#define CVTO_THREADS 262144
#define CVTO_BLOCKS (CVTO_THREADS / 256) // 1024
__global__ void prep_kernel(const float* __restrict__ x,
                            const float* __restrict__ wr,
                            float* __restrict__ logits_out,
                            __half* __restrict__ x16,
                            const float* __restrict__ wout, __half* __restrict__ dwout) {
    if (blockIdx.x < NT) {
        // ---- router + x convert ----
        int t = blockIdx.x;
        int w = threadIdx.x >> 5;
        int l = threadIdx.x & 31;
        const float* xr = x + (size_t)t * ND;
        const float* wrow = wr + w * ND;
        float s = 0.f;
        #pragma unroll 8
        for (int j = l; j < ND; j += 32) s += xr[j] * wrow[j];
        #pragma unroll
        for (int o = 16; o > 0; o >>= 1) s += __shfl_xor_sync(0xffffffffu, s, o);
        __shared__ float lg[NE];
        if (l == 0) { lg[w] = s; logits_out[(size_t)t * NE + w] = s; }

        {
            int j = threadIdx.x * 4;
            float4 v = *reinterpret_cast<const float4*>(xr + j);
            __half2* dst = reinterpret_cast<__half2*>(x16 + (size_t)t * ND + j);
            dst[0] = __floats2half2_rn(v.x, v.y);
            dst[1] = __floats2half2_rn(v.z, v.w);
        }

        __syncthreads();
        if (threadIdx.x == 0) {
            int i0 = 0; float v0 = lg[0];
            #pragma unroll
            for (int e = 1; e < NE; ++e) if (lg[e] > v0) { v0 = lg[e]; i0 = e; }
            int i1 = -1; float v1 = -INFINITY;
            #pragma unroll
            for (int e = 0; e < NE; ++e) if (e != i0 && lg[e] > v1) { v1 = lg[e]; i1 = e; }
            float e1 = expf(v1 - v0);
            float inv = 1.f / (1.f + e1);
            int p0 = atomicAdd(&g_cnt[i0], 1);
            g_tokslot[i0 * NT + p0] = t * 2;
            g_gate[i0 * NT + p0]    = inv;
            int p1 = atomicAdd(&g_cnt[i1], 1);
            g_tokslot[i1 * NT + p1] = t * 2 + 1;
            g_gate[i1 * NT + p1]    = e1 * inv;
        }
    } else {
        // ---- w_out convert: exactly 4 float4 per thread ----
        int tid = (blockIdx.x - NT) * blockDim.x + threadIdx.x;
        #pragma unroll
        for (int u = 0; u < 4; ++u) {
            int j = tid + u * CVTO_THREADS;
            float4 v = reinterpret_cast<const float4*>(wout)[j];
            reinterpret_cast<__half2*>(dwout)[2 * j]     = __floats2half2_rn(v.x, v.y);
            reinterpret_cast<__half2*>(dwout)[2 * j + 1] = __floats2half2_rn(v.z, v.w);
        }
    }
}

// Shared-mem geometry: row = 64B (32 halfs), chunk = 16B, swizzle c^=((row>>1)&3).
// Stage = A(128x32h, 8KB) + B(128x32h, 8KB) = 16KB; 3 stages = 48KB (static).
#define STAGE_BYTES 16384

// =====================================================================
// ffn1: C[128 x 128] = A(gathered x16 rows) @ B^T, fp16 mma, K = 1024.
// A: cp.async fp16 (g_x16). B: w_in read fp32 DIRECTLY from global,
// converted in-register (ldgcvt8), STS'd one iteration later (register
// pipeline covers LDG latency). No materialized fp16 w_in.
// B tile rows interleaved per-warp (a/b halves pair thread-locally).
// Epilogue: h = silu(a)*b -> g_h16, all-register.
// =====================================================================
__global__ void __launch_bounds__(256, 2)
ffn1_h(const float* __restrict__ w_in) {
    __shared__ __align__(128) uint8_t smem[3 * STAGE_BYTES];
    int e = blockIdx.z;
    int cnt = g_cnt[e];
    int m0 = blockIdx.y * 128;
    if (m0 >= cnt) return;
    int n0 = blockIdx.x * 64;

    uint32_t sb = smem_u32(smem);
    int t = threadIdx.x;
    int lane = t & 31, wid = t >> 5;
    int wm = wid & 1, wn = wid >> 1;          // warp grid 2(M) x 4(N)
    int grp = lane >> 2, tig = lane & 3;
    int rA = (lane & 7) + ((lane >> 3) & 1) * 8;   // ldmatrix row-in-16
    int csel = lane >> 4;                          // ldmatrix chunk select

    int lr = t >> 2;             // 0..63
    int lc = t & 3;
    int r0 = m0 + lr, r1 = r0 + 64;
    int rc0 = r0 < cnt ? r0 : cnt - 1;
    int rc1 = r1 < cnt ? r1 : cnt - 1;
    const __half* asrc0 = g_x16 + (size_t)(g_tokslot[e * NT + rc0] >> 1) * ND + lc * 8;
    const __half* asrc1 = g_x16 + (size_t)(g_tokslot[e * NT + rc1] >> 1) * ND + lc * 8;
    // interleaved B-row mapping for tile rows nn0=lr, nn1=lr+64
    int nn0 = lr, nn1 = lr + 64;
    int j0 = nn0 & 31, j1 = nn1 & 31;
    int brow0 = (j0 < 16) ? (n0 + (nn0 >> 5) * 16 + j0) : (NH + n0 + (nn0 >> 5) * 16 + j0 - 16);
    int brow1 = (j1 < 16) ? (n0 + (nn1 >> 5) * 16 + j1) : (NH + n0 + (nn1 >> 5) * 16 + j1 - 16);
    const float* bfsrc0 = w_in + ((size_t)e * (2 * NH) + brow0) * ND + lc * 8;
    const float* bfsrc1 = w_in + ((size_t)e * (2 * NH) + brow1) * ND + lc * 8;
    uint32_t swc = (uint32_t)((lc ^ ((lr >> 1) & 3)) << 4);
    uint32_t dA0 = lr * 64 + swc;
    uint32_t dA1 = dA0 + 4096;
    char* smemc = (char*)smem;

    uint32_t relA[4], relB0, relB1;
    #pragma unroll
    for (int mt = 0; mt < 4; ++mt) {
        int row = wm * 64 + mt * 16 + rA;
        relA[mt] = (uint32_t)(row * 64) + ((uint32_t)((((row >> 1) & 3) ^ csel)) << 4);
    }
    {
        int row = wn * 32 + rA;
        relB0 = 8192u + (uint32_t)(row * 64) + ((uint32_t)((((row >> 1) & 3) ^ csel)) << 4);
        row += 16;
        relB1 = 8192u + (uint32_t)(row * 64) + ((uint32_t)((((row >> 1) & 3) ^ csel)) << 4);
    }

    float acc[4][4][4];
    #pragma unroll
    for (int i = 0; i < 4; ++i)
        #pragma unroll
        for (int j = 0; j < 4; ++j)
            #pragma unroll
            for (int q = 0; q < 4; ++q) acc[i][j][q] = 0.f;

    // preamble: B stages 0,1 direct (LDG fp32 -> cvt -> STS); hold stage 2 in regs
    #pragma unroll
    for (int s = 0; s < 2; ++s) {
        uint4 b0 = ldgcvt8(bfsrc0 + s * 32);
        uint4 b1 = ldgcvt8(bfsrc1 + s * 32);
        *(uint4*)(smemc + s * STAGE_BYTES + 8192 + dA0) = b0;
        *(uint4*)(smemc + s * STAGE_BYTES + 8192 + dA1) = b1;
    }
    uint4 bh0 = ldgcvt8(bfsrc0 + 64);
    uint4 bh1 = ldgcvt8(bfsrc1 + 64);
    // A stages 0,1 via cp.async
    #pragma unroll
    for (int s = 0; s < 2; ++s) {
        uint32_t st = sb + s * STAGE_BYTES;
        CPA16(st + dA0, asrc0 + s * 32);
        CPA16(st + dA1, asrc1 + s * 32);
        CPCOMMIT();
    }

    const int NK = ND / 32;   // 32
    int stage = 0;
    for (int kt = 0; kt < NK; ++kt) {
        if (kt < NK - 1) { CPWAIT(1); } else { CPWAIT(0); }
        __syncthreads();
        if (kt + 2 < NK) {
            int s2 = (kt + 2) % 3;
            uint32_t st = sb + s2 * STAGE_BYTES;
            int off = (kt + 2) * 32;
            CPA16(st + dA0, asrc0 + off);
            CPA16(st + dA1, asrc1 + off);
            CPCOMMIT();
            // STS held B (loaded last iteration for stage kt+2)
            *(uint4*)(smemc + s2 * STAGE_BYTES + 8192 + dA0) = bh0;
            *(uint4*)(smemc + s2 * STAGE_BYTES + 8192 + dA1) = bh1;
        }
        if (kt + 3 < NK) {
            bh0 = ldgcvt8(bfsrc0 + (kt + 3) * 32);
            bh1 = ldgcvt8(bfsrc1 + (kt + 3) * 32);
        }
        uint32_t As = sb + stage * STAGE_BYTES;
        uint32_t B0a[4], B1a[4], B0b[4], B1b[4];
        LDM_X4(B0a[0], B0a[1], B0a[2], B0a[3], As + relB0);
        LDM_X4(B1a[0], B1a[1], B1a[2], B1a[3], As + relB1);
        LDM_X4(B0b[0], B0b[1], B0b[2], B0b[3], As + (relB0 ^ 32u));
        LDM_X4(B1b[0], B1b[1], B1b[2], B1b[3], As + (relB1 ^ 32u));
        #pragma unroll
        for (int ks = 0; ks < 2; ++ks) {
            uint32_t kx = (uint32_t)(ks << 5);
            const uint32_t* B0 = ks ? B0b : B0a;
            const uint32_t* B1 = ks ? B1b : B1a;
            uint32_t a[4][4];
            #pragma unroll
            for (int mt = 0; mt < 4; ++mt)
                LDM_X4(a[mt][0], a[mt][1], a[mt][2], a[mt][3], As + (relA[mt] ^ kx));
            #pragma unroll
            for (int mt = 0; mt < 4; ++mt) {
                MMA16(acc[mt][0], a[mt], B0[0], B0[2]);
                MMA16(acc[mt][1], a[mt], B0[1], B0[3]);
                MMA16(acc[mt][2], a[mt], B1[0], B1[2]);
                MMA16(acc[mt][3], a[mt], B1[1], B1[3]);
            }
        }
        stage = stage + 1; if (stage == 3) stage = 0;
    }

    // epilogue: acc[mt][nt] (a-cols) pairs with acc[mt][nt+2] (b-cols), nt in {0,1}.
    #pragma unroll
    for (int mt = 0; mt < 4; ++mt) {
        #pragma unroll
        for (int hf = 0; hf < 2; ++hf) {
            int row = wm * 64 + mt * 16 + grp + hf * 8;
            int rr = m0 + row;
            if (rr < cnt) {
                __half* dst = g_h16 + ((size_t)e * NT + rr) * NH + n0 + wn * 16;
                #pragma unroll
                for (int nt = 0; nt < 2; ++nt) {
                    float a0 = acc[mt][nt][hf * 2 + 0];
                    float a1 = acc[mt][nt][hf * 2 + 1];
                    float b0 = acc[mt][nt + 2][hf * 2 + 0];
                    float b1 = acc[mt][nt + 2][hf * 2 + 1];
                    float h0 = a0 / (1.f + __expf(-a0)) * b0;
                    float h1 = a1 / (1.f + __expf(-a1)) * b1;
                    *(__half2*)(dst + nt * 8 + 2 * tig) = __floats2half2_rn(h0, h1);
                }
            }
        }
    }
}

// =====================================================================
// ffn2: C[128 x 128] = g_h16 rows @ w_out16 rows^T, K = 512.  (R12 config)
// Epilogue: gate-scale, scatter rows to g_y[tokslot] (fp32).
// =====================================================================
__global__ void __launch_bounds__(256, 2)
ffn2_h(void) {
    __shared__ __align__(128) uint8_t smem[3 * STAGE_BYTES];
    int e = blockIdx.z;
    int cnt = g_cnt[e];
    int m0 = blockIdx.y * 128;
    if (m0 >= cnt) return;
    int n0 = blockIdx.x * 128;

    uint32_t sb = smem_u32(smem);
    int t = threadIdx.x;
    int lane = t & 31, wid = t >> 5;
    int wm = wid & 1, wn = wid >> 1;
    int grp = lane >> 2, tig = lane & 3;
    int rA = (lane & 7) + ((lane >> 3) & 1) * 8;
    int csel = lane >> 4;

    int lr = t >> 2;
    int lc = t & 3;
    int r0 = m0 + lr, r1 = r0 + 64;
    int rc0 = r0 < cnt ? r0 : cnt - 1;
    int rc1 = r1 < cnt ? r1 : cnt - 1;
    const __half* asrc0 = g_h16 + ((size_t)e * NT + rc0) * NH + lc * 8;
    const __half* asrc1 = g_h16 + ((size_t)e * NT + rc1) * NH + lc * 8;
    const __half* bsrc0 = g_wout16 + ((size_t)e * ND + n0 + lr) * NH + lc * 8;
    const __half* bsrc1 = g_wout16 + ((size_t)e * ND + n0 + lr + 64) * NH + lc * 8;
    uint32_t swc = (uint32_t)((lc ^ ((lr >> 1) & 3)) << 4);
    uint32_t dA0 = lr * 64 + swc;
    uint32_t dA1 = dA0 + 4096;

    uint32_t relA[4], relB0, relB1;
    #pragma unroll
    for (int mt = 0; mt < 4; ++mt) {
        int row = wm * 64 + mt * 16 + rA;
        relA[mt] = (uint32_t)(row * 64) + ((uint32_t)((((row >> 1) & 3) ^ csel)) << 4);
    }
    {
        int row = wn * 32 + rA;
        relB0 = 8192u + (uint32_t)(row * 64) + ((uint32_t)((((row >> 1) & 3) ^ csel)) << 4);
        row += 16;
        relB1 = 8192u + (uint32_t)(row * 64) + ((uint32_t)((((row >> 1) & 3) ^ csel)) << 4);
    }

    float acc[4][4][4];
    #pragma unroll
    for (int i = 0; i < 4; ++i)
        #pragma unroll
        for (int j = 0; j < 4; ++j)
            #pragma unroll
            for (int q = 0; q < 4; ++q) acc[i][j][q] = 0.f;

    #pragma unroll
    for (int s = 0; s < 2; ++s) {
        uint32_t st = sb + s * STAGE_BYTES;
        CPA16(st + dA0, asrc0 + s * 32);
        CPA16(st + dA1, asrc1 + s * 32);
        CPA16(st + 8192 + dA0, bsrc0 + s * 32);
        CPA16(st + 8192 + dA1, bsrc1 + s * 32);
        CPCOMMIT();
    }

    const int NK = NH / 32;   // 16
    int stage = 0;
    for (int kt = 0; kt < NK; ++kt) {
        if (kt < NK - 1) { CPWAIT(1); } else { CPWAIT(0); }
        __syncthreads();
        if (kt + 2 < NK) {
            uint32_t st = sb + ((kt + 2) % 3) * STAGE_BYTES;
            int off = (kt + 2) * 32;
            CPA16(st + dA0, asrc0 + off);
            CPA16(st + dA1, asrc1 + off);
            CPA16(st + 8192 + dA0, bsrc0 + off);
            CPA16(st + 8192 + dA1, bsrc1 + off);
            CPCOMMIT();
        }
        uint32_t As = sb + stage * STAGE_BYTES;
        uint32_t B0a[4], B1a[4], B0b[4], B1b[4];
        LDM_X4(B0a[0], B0a[1], B0a[2], B0a[3], As + relB0);
        LDM_X4(B1a[0], B1a[1], B1a[2], B1a[3], As + relB1);
        LDM_X4(B0b[0], B0b[1], B0b[2], B0b[3], As + (relB0 ^ 32u));
        LDM_X4(B1b[0], B1b[1], B1b[2], B1b[3], As + (relB1 ^ 32u));
        #pragma unroll
        for (int ks = 0; ks < 2; ++ks) {
            uint32_t kx = (uint32_t)(ks << 5);
            const uint32_t* B0 = ks ? B0b : B0a;
            const uint32_t* B1 = ks ? B1b : B1a;
            uint32_t a[4][4];
            #pragma unroll
            for (int mt = 0; mt < 4; ++mt)
                LDM_X4(a[mt][0], a[mt][1], a[mt][2], a[mt][3], As + (relA[mt] ^ kx));
            #pragma unroll
            for (int mt = 0; mt < 4; ++mt) {
                MMA16(acc[mt][0], a[mt], B0[0], B0[2]);
                MMA16(acc[mt][1], a[mt], B0[1], B0[3]);
                MMA16(acc[mt][2], a[mt], B1[0], B1[2]);
                MMA16(acc[mt][3], a[mt], B1[1], B1[3]);
            }
        }
        stage = stage + 1; if (stage == 3) stage = 0;
    }

    #pragma unroll
    for (int mt = 0; mt < 4; ++mt) {
        #pragma unroll
        for (int hf = 0; hf < 2; ++hf) {
            int row = wm * 64 + mt * 16 + grp + hf * 8;
            int rr = m0 + row;
            if (rr < cnt) {
                int   ts = g_tokslot[e * NT + rr];
                float gt = g_gate[e * NT + rr];
                float* dst = g_y + (size_t)ts * ND + n0;
                #pragma unroll
                for (int nt = 0; nt < 4; ++nt) {
                    int col = wn * 32 + nt * 8 + 2 * tig;
                    float2 v = make_float2(acc[mt][nt][hf * 2 + 0] * gt,
                                           acc[mt][nt][hf * 2 + 1] * gt);
                    *(float2*)(dst + col) = v;
                }
            }
        }
    }
}

// out[t] = y[2t] + y[2t+1]; 2 float4 per thread (R12 version).
// Also re-zeroes g_cnt for the next graph replay.
__global__ void combine_kernel(float* __restrict__ out) {
    if (blockIdx.x == 0 && threadIdx.x < NE) g_cnt[threadIdx.x] = 0;
    int base = blockIdx.x * blockDim.x + threadIdx.x;
    const int half = NT * ND / 8;   // float4s per pass
    const float4* y4 = reinterpret_cast<const float4*>(g_y);
    #pragma unroll
    for (int u = 0; u < 2; ++u) {
        int i = base + u * half;
        int t = i >> 8, c = i & 255;
        float4 a = y4[(size_t)(2 * t) * 256 + c];
        float4 b = y4[(size_t)(2 * t + 1) * 256 + c];
        reinterpret_cast<float4*>(out)[i] =
            make_float4(a.x + b.x, a.y + b.y, a.z + b.z, a.w + b.w);
    }
}

extern "C" void kernel_launch(void* const* d_in, const int* in_sizes, int n_in,
                              void* d_out, int out_size) {
    const float* x     = (const float*)d_in[0];
    const float* wr    = (const float*)d_in[1];
    const float* w_in  = (const float*)d_in[2];
    const float* w_out = (const float*)d_in[3];
    float* out = (float*)d_out;

    float* logits;
    if (out_size >= NT * ND + NT * NE) {
        logits = out + (size_t)NT * ND;
    } else {
        cudaGetSymbolAddress((void**)&logits, g_logits_scratch);
    }

    __half *px16, *pwout16;
    cudaGetSymbolAddress((void**)&px16, g_x16);
    cudaGetSymbolAddress((void**)&pwout16, g_wout16);

    prep_kernel<<<NT + CVTO_BLOCKS, 256>>>(x, wr, logits, px16, w_out, pwout16);
    ffn1_h<<<dim3(NH / 64, NT / 128, NE), 256>>>(w_in);
    ffn2_h<<<dim3(ND / 128, NT / 128, NE), 256>>>();
    combine_kernel<<<(NT * ND / 8 + 255) / 256, 256>>>(out);
}

// round 15
// speedup vs baseline: 1.5523x; 1.5523x over previous
#include <cuda_runtime.h>
#include <cuda_fp16.h>
#include <math.h>
#include <stdint.h>

#define NT 4096      // tokens = B*S
#define ND 1024      // hidden
#define NH 512       // intermediate
#define NE 8         // experts

// ---- device scratch (static; no allocations allowed) ----
__device__ int    g_cnt[NE];          // zero-init at load; re-zeroed by combine_kernel each call
__device__ int    g_tokslot[NE * NT];
__device__ float  g_gate[NE * NT];
__device__ __half g_x16[(size_t)NT * ND];
__device__ __half g_win16[(size_t)NE * 2 * NH * ND];
__device__ __half g_wout16[(size_t)NE * ND * NH];
__device__ __half g_h16[(size_t)NE * NT * NH];
__device__ float  g_y[(size_t)NT * 2 * ND];
__device__ float  g_logits_scratch[(size_t)NT * NE];

// ======================= helpers =======================
__device__ __forceinline__ uint32_t smem_u32(const void* p) {
    uint32_t a;
    asm("{ .reg .u64 t; cvta.to.shared.u64 t, %1; cvt.u32.u64 %0, t; }" : "=r"(a) : "l"(p));
    return a;
}
#define CPA16(dst, src) asm volatile("cp.async.cg.shared.global [%0], [%1], 16;" :: "r"(dst), "l"(src))
#define CPCOMMIT()      asm volatile("cp.async.commit_group;")
#define CPWAIT(n)       asm volatile("cp.async.wait_group %0;" :: "n"(n))
#define LDM_X4(r0, r1, r2, r3, addr) \
    asm volatile("ldmatrix.sync.aligned.m8n8.x4.shared.b16 {%0,%1,%2,%3}, [%4];" \
        : "=r"(r0), "=r"(r1), "=r"(r2), "=r"(r3) : "r"(addr))
#define MMA16(d, a, b0, b1) \
    asm volatile("mma.sync.aligned.m16n8k16.row.col.f32.f16.f16.f32 " \
        "{%0,%1,%2,%3}, {%4,%5,%6,%7}, {%8,%9}, {%0,%1,%2,%3};" \
        : "+f"((d)[0]), "+f"((d)[1]), "+f"((d)[2]), "+f"((d)[3]) \
        : "r"((a)[0]), "r"((a)[1]), "r"((a)[2]), "r"((a)[3]), "r"(b0), "r"(b1))

// =====================================================================
// prep_kernel: blocks [0, NT) = router (+x fp16 convert);
//              blocks [NT, NT + CVT_BLOCKS) = weight fp32->fp16 convert.
#define NWI (NE * 2 * NH * ND / 4)
#define NWO (NE * ND * NH / 4)
#define CVT_THREADS 524288
#define CVT_BLOCKS (CVT_THREADS / 256)
__global__ void prep_kernel(const float* __restrict__ x,
                            const float* __restrict__ wr,
                            float* __restrict__ logits_out,
                            __half* __restrict__ x16,
                            const float* __restrict__ win, __half* __restrict__ dwin,
                            const float* __restrict__ wout, __half* __restrict__ dwout) {
    if (blockIdx.x < NT) {
        // ---- router + x convert ----
        int t = blockIdx.x;
        int w = threadIdx.x >> 5;
        int l = threadIdx.x & 31;
        const float* xr = x + (size_t)t * ND;
        const float* wrow = wr + w * ND;
        float s = 0.f;
        #pragma unroll 8
        for (int j = l; j < ND; j += 32) s += xr[j] * wrow[j];
        #pragma unroll
        for (int o = 16; o > 0; o >>= 1) s += __shfl_xor_sync(0xffffffffu, s, o);
        __shared__ float lg[NE];
        if (l == 0) { lg[w] = s; logits_out[(size_t)t * NE + w] = s; }

        {
            int j = threadIdx.x * 4;
            float4 v = *reinterpret_cast<const float4*>(xr + j);
            __half2* dst = reinterpret_cast<__half2*>(x16 + (size_t)t * ND + j);
            dst[0] = __floats2half2_rn(v.x, v.y);
            dst[1] = __floats2half2_rn(v.z, v.w);
        }

        __syncthreads();
        if (threadIdx.x == 0) {
            int i0 = 0; float v0 = lg[0];
            #pragma unroll
            for (int e = 1; e < NE; ++e) if (lg[e] > v0) { v0 = lg[e]; i0 = e; }
            int i1 = -1; float v1 = -INFINITY;
            #pragma unroll
            for (int e = 0; e < NE; ++e) if (e != i0 && lg[e] > v1) { v1 = lg[e]; i1 = e; }
            float e1 = expf(v1 - v0);
            float inv = 1.f / (1.f + e1);
            int p0 = atomicAdd(&g_cnt[i0], 1);
            g_tokslot[i0 * NT + p0] = t * 2;
            g_gate[i0 * NT + p0]    = inv;
            int p1 = atomicAdd(&g_cnt[i1], 1);
            g_tokslot[i1 * NT + p1] = t * 2 + 1;
            g_gate[i1 * NT + p1]    = e1 * inv;
        }
    } else {
        // ---- weight convert: exactly 6 float4 per thread ----
        int tid = (blockIdx.x - NT) * blockDim.x + threadIdx.x;
        #pragma unroll
        for (int u = 0; u < 6; ++u) {
            int i = tid + u * CVT_THREADS;
            const float* s; __half* d; int j;
            if (i < NWI) { s = win; d = dwin; j = i; }
            else         { s = wout; d = dwout; j = i - NWI; }
            float4 v = reinterpret_cast<const float4*>(s)[j];
            reinterpret_cast<__half2*>(d)[2 * j]     = __floats2half2_rn(v.x, v.y);
            reinterpret_cast<__half2*>(d)[2 * j + 1] = __floats2half2_rn(v.z, v.w);
        }
    }
}

// Shared-mem geometry: row = 64B (32 halfs), chunk = 16B, swizzle c^=((row>>1)&3).
// Stage = A(128x32h, 8KB) + B(128x32h, 8KB) = 16KB; 3 stages = 48KB (static).
#define STAGE_BYTES 16384

// =====================================================================
// ffn1: C[128 x 128] = A(gathered x16 rows) @ B^T, fp16 mma, K = 1024.
// B tile rows interleaved per-warp (a/b halves pair thread-locally).
// Both ks-halves' B fragments hoisted right after the sync.
// Epilogue: h = silu(a)*b -> g_h16, all-register.
// =====================================================================
__global__ void __launch_bounds__(256, 2)
ffn1_h(void) {
    __shared__ __align__(128) uint8_t smem[3 * STAGE_BYTES];
    int e = blockIdx.z;
    int cnt = g_cnt[e];
    int m0 = blockIdx.y * 128;
    if (m0 >= cnt) return;
    int n0 = blockIdx.x * 64;

    uint32_t sb = smem_u32(smem);
    int t = threadIdx.x;
    int lane = t & 31, wid = t >> 5;
    int wm = wid & 1, wn = wid >> 1;          // warp grid 2(M) x 4(N)
    int grp = lane >> 2, tig = lane & 3;
    int rA = (lane & 7) + ((lane >> 3) & 1) * 8;   // ldmatrix row-in-16
    int csel = lane >> 4;                          // ldmatrix chunk select

    int lr = t >> 2;             // 0..63
    int lc = t & 3;
    int r0 = m0 + lr, r1 = r0 + 64;
    int rc0 = r0 < cnt ? r0 : cnt - 1;
    int rc1 = r1 < cnt ? r1 : cnt - 1;
    const __half* asrc0 = g_x16 + (size_t)(g_tokslot[e * NT + rc0] >> 1) * ND + lc * 8;
    const __half* asrc1 = g_x16 + (size_t)(g_tokslot[e * NT + rc1] >> 1) * ND + lc * 8;
    // interleaved B-row mapping for tile rows nn0=lr, nn1=lr+64
    int nn0 = lr, nn1 = lr + 64;
    int j0 = nn0 & 31, j1 = nn1 & 31;
    int brow0 = (j0 < 16) ? (n0 + (nn0 >> 5) * 16 + j0) : (NH + n0 + (nn0 >> 5) * 16 + j0 - 16);
    int brow1 = (j1 < 16) ? (n0 + (nn1 >> 5) * 16 + j1) : (NH + n0 + (nn1 >> 5) * 16 + j1 - 16);
    const __half* bsrc0 = g_win16 + ((size_t)e * (2 * NH) + brow0) * ND + lc * 8;
    const __half* bsrc1 = g_win16 + ((size_t)e * (2 * NH) + brow1) * ND + lc * 8;
    uint32_t swc = (uint32_t)((lc ^ ((lr >> 1) & 3)) << 4);
    uint32_t dA0 = lr * 64 + swc;
    uint32_t dA1 = dA0 + 4096;

    uint32_t relA[4], relB0, relB1;
    #pragma unroll
    for (int mt = 0; mt < 4; ++mt) {
        int row = wm * 64 + mt * 16 + rA;
        relA[mt] = (uint32_t)(row * 64) + ((uint32_t)((((row >> 1) & 3) ^ csel)) << 4);
    }
    {
        int row = wn * 32 + rA;
        relB0 = 8192u + (uint32_t)(row * 64) + ((uint32_t)((((row >> 1) & 3) ^ csel)) << 4);
        row += 16;
        relB1 = 8192u + (uint32_t)(row * 64) + ((uint32_t)((((row >> 1) & 3) ^ csel)) << 4);
    }

    float acc[4][4][4];
    #pragma unroll
    for (int i = 0; i < 4; ++i)
        #pragma unroll
        for (int j = 0; j < 4; ++j)
            #pragma unroll
            for (int q = 0; q < 4; ++q) acc[i][j][q] = 0.f;

    #pragma unroll
    for (int s = 0; s < 2; ++s) {
        uint32_t st = sb + s * STAGE_BYTES;
        CPA16(st + dA0, asrc0 + s * 32);
        CPA16(st + dA1, asrc1 + s * 32);
        CPA16(st + 8192 + dA0, bsrc0 + s * 32);
        CPA16(st + 8192 + dA1, bsrc1 + s * 32);
        CPCOMMIT();
    }

    const int NK = ND / 32;   // 32
    int stage = 0;
    for (int kt = 0; kt < NK; ++kt) {
        if (kt < NK - 1) { CPWAIT(1); } else { CPWAIT(0); }
        __syncthreads();
        if (kt + 2 < NK) {
            uint32_t st = sb + ((kt + 2) % 3) * STAGE_BYTES;
            int off = (kt + 2) * 32;
            CPA16(st + dA0, asrc0 + off);
            CPA16(st + dA1, asrc1 + off);
            CPA16(st + 8192 + dA0, bsrc0 + off);
            CPA16(st + 8192 + dA1, bsrc1 + off);
            CPCOMMIT();
        }
        uint32_t As = sb + stage * STAGE_BYTES;
        uint32_t B0a[4], B1a[4], B0b[4], B1b[4];
        LDM_X4(B0a[0], B0a[1], B0a[2], B0a[3], As + relB0);
        LDM_X4(B1a[0], B1a[1], B1a[2], B1a[3], As + relB1);
        LDM_X4(B0b[0], B0b[1], B0b[2], B0b[3], As + (relB0 ^ 32u));
        LDM_X4(B1b[0], B1b[1], B1b[2], B1b[3], As + (relB1 ^ 32u));
        #pragma unroll
        for (int ks = 0; ks < 2; ++ks) {
            uint32_t kx = (uint32_t)(ks << 5);
            const uint32_t* B0 = ks ? B0b : B0a;
            const uint32_t* B1 = ks ? B1b : B1a;
            uint32_t a[4][4];
            #pragma unroll
            for (int mt = 0; mt < 4; ++mt)
                LDM_X4(a[mt][0], a[mt][1], a[mt][2], a[mt][3], As + (relA[mt] ^ kx));
            #pragma unroll
            for (int mt = 0; mt < 4; ++mt) {
                MMA16(acc[mt][0], a[mt], B0[0], B0[2]);
                MMA16(acc[mt][1], a[mt], B0[1], B0[3]);
                MMA16(acc[mt][2], a[mt], B1[0], B1[2]);
                MMA16(acc[mt][3], a[mt], B1[1], B1[3]);
            }
        }
        stage = stage + 1; if (stage == 3) stage = 0;
    }

    // epilogue: acc[mt][nt] (a-cols) pairs with acc[mt][nt+2] (b-cols), nt in {0,1}.
    #pragma unroll
    for (int mt = 0; mt < 4; ++mt) {
        #pragma unroll
        for (int hf = 0; hf < 2; ++hf) {
            int row = wm * 64 + mt * 16 + grp + hf * 8;
            int rr = m0 + row;
            if (rr < cnt) {
                __half* dst = g_h16 + ((size_t)e * NT + rr) * NH + n0 + wn * 16;
                #pragma unroll
                for (int nt = 0; nt < 2; ++nt) {
                    float a0 = acc[mt][nt][hf * 2 + 0];
                    float a1 = acc[mt][nt][hf * 2 + 1];
                    float b0 = acc[mt][nt + 2][hf * 2 + 0];
                    float b1 = acc[mt][nt + 2][hf * 2 + 1];
                    float h0 = a0 / (1.f + __expf(-a0)) * b0;
                    float h1 = a1 / (1.f + __expf(-a1)) * b1;
                    *(__half2*)(dst + nt * 8 + 2 * tig) = __floats2half2_rn(h0, h1);
                }
            }
        }
    }
}

// =====================================================================
// ffn2: C[128 x 128] = g_h16 rows @ w_out16 rows^T, K = 512.
// Epilogue: gate-scale, scatter rows to g_y[tokslot].
// =====================================================================
__global__ void __launch_bounds__(256, 2)
ffn2_h(void) {
    __shared__ __align__(128) uint8_t smem[3 * STAGE_BYTES];
    int e = blockIdx.z;
    int cnt = g_cnt[e];
    int m0 = blockIdx.y * 128;
    if (m0 >= cnt) return;
    int n0 = blockIdx.x * 128;

    uint32_t sb = smem_u32(smem);
    int t = threadIdx.x;
    int lane = t & 31, wid = t >> 5;
    int wm = wid & 1, wn = wid >> 1;
    int grp = lane >> 2, tig = lane & 3;
    int rA = (lane & 7) + ((lane >> 3) & 1) * 8;
    int csel = lane >> 4;

    int lr = t >> 2;
    int lc = t & 3;
    int r0 = m0 + lr, r1 = r0 + 64;
    int rc0 = r0 < cnt ? r0 : cnt - 1;
    int rc1 = r1 < cnt ? r1 : cnt - 1;
    const __half* asrc0 = g_h16 + ((size_t)e * NT + rc0) * NH + lc * 8;
    const __half* asrc1 = g_h16 + ((size_t)e * NT + rc1) * NH + lc * 8;
    const __half* bsrc0 = g_wout16 + ((size_t)e * ND + n0 + lr) * NH + lc * 8;
    const __half* bsrc1 = g_wout16 + ((size_t)e * ND + n0 + lr + 64) * NH + lc * 8;
    uint32_t swc = (uint32_t)((lc ^ ((lr >> 1) & 3)) << 4);
    uint32_t dA0 = lr * 64 + swc;
    uint32_t dA1 = dA0 + 4096;

    uint32_t relA[4], relB0, relB1;
    #pragma unroll
    for (int mt = 0; mt < 4; ++mt) {
        int row = wm * 64 + mt * 16 + rA;
        relA[mt] = (uint32_t)(row * 64) + ((uint32_t)((((row >> 1) & 3) ^ csel)) << 4);
    }
    {
        int row = wn * 32 + rA;
        relB0 = 8192u + (uint32_t)(row * 64) + ((uint32_t)((((row >> 1) & 3) ^ csel)) << 4);
        row += 16;
        relB1 = 8192u + (uint32_t)(row * 64) + ((uint32_t)((((row >> 1) & 3) ^ csel)) << 4);
    }

    float acc[4][4][4];
    #pragma unroll
    for (int i = 0; i < 4; ++i)
        #pragma unroll
        for (int j = 0; j < 4; ++j)
            #pragma unroll
            for (int q = 0; q < 4; ++q) acc[i][j][q] = 0.f;

    #pragma unroll
    for (int s = 0; s < 2; ++s) {
        uint32_t st = sb + s * STAGE_BYTES;
        CPA16(st + dA0, asrc0 + s * 32);
        CPA16(st + dA1, asrc1 + s * 32);
        CPA16(st + 8192 + dA0, bsrc0 + s * 32);
        CPA16(st + 8192 + dA1, bsrc1 + s * 32);
        CPCOMMIT();
    }

    const int NK = NH / 32;   // 16
    int stage = 0;
    for (int kt = 0; kt < NK; ++kt) {
        if (kt < NK - 1) { CPWAIT(1); } else { CPWAIT(0); }
        __syncthreads();
        if (kt + 2 < NK) {
            uint32_t st = sb + ((kt + 2) % 3) * STAGE_BYTES;
            int off = (kt + 2) * 32;
            CPA16(st + dA0, asrc0 + off);
            CPA16(st + dA1, asrc1 + off);
            CPA16(st + 8192 + dA0, bsrc0 + off);
            CPA16(st + 8192 + dA1, bsrc1 + off);
            CPCOMMIT();
        }
        uint32_t As = sb + stage * STAGE_BYTES;
        uint32_t B0a[4], B1a[4], B0b[4], B1b[4];
        LDM_X4(B0a[0], B0a[1], B0a[2], B0a[3], As + relB0);
        LDM_X4(B1a[0], B1a[1], B1a[2], B1a[3], As + relB1);
        LDM_X4(B0b[0], B0b[1], B0b[2], B0b[3], As + (relB0 ^ 32u));
        LDM_X4(B1b[0], B1b[1], B1b[2], B1b[3], As + (relB1 ^ 32u));
        #pragma unroll
        for (int ks = 0; ks < 2; ++ks) {
            uint32_t kx = (uint32_t)(ks << 5);
            const uint32_t* B0 = ks ? B0b : B0a;
            const uint32_t* B1 = ks ? B1b : B1a;
            uint32_t a[4][4];
            #pragma unroll
            for (int mt = 0; mt < 4; ++mt)
                LDM_X4(a[mt][0], a[mt][1], a[mt][2], a[mt][3], As + (relA[mt] ^ kx));
            #pragma unroll
            for (int mt = 0; mt < 4; ++mt) {
                MMA16(acc[mt][0], a[mt], B0[0], B0[2]);
                MMA16(acc[mt][1], a[mt], B0[1], B0[3]);
                MMA16(acc[mt][2], a[mt], B1[0], B1[2]);
                MMA16(acc[mt][3], a[mt], B1[1], B1[3]);
            }
        }
        stage = stage + 1; if (stage == 3) stage = 0;
    }

    #pragma unroll
    for (int mt = 0; mt < 4; ++mt) {
        #pragma unroll
        for (int hf = 0; hf < 2; ++hf) {
            int row = wm * 64 + mt * 16 + grp + hf * 8;
            int rr = m0 + row;
            if (rr < cnt) {
                int   ts = g_tokslot[e * NT + rr];
                float gt = g_gate[e * NT + rr];
                float* dst = g_y + (size_t)ts * ND + n0;
                #pragma unroll
                for (int nt = 0; nt < 4; ++nt) {
                    int col = wn * 32 + nt * 8 + 2 * tig;
                    float2 v = make_float2(acc[mt][nt][hf * 2 + 0] * gt,
                                           acc[mt][nt][hf * 2 + 1] * gt);
                    *(float2*)(dst + col) = v;
                }
            }
        }
    }
}

// out[t] = y[2t] + y[2t+1]; 2 float4 per thread (MLP=2).
// Also re-zeroes g_cnt for the next graph replay.
__global__ void combine_kernel(float* __restrict__ out) {
    if (blockIdx.x == 0 && threadIdx.x < NE) g_cnt[threadIdx.x] = 0;
    int base = blockIdx.x * blockDim.x + threadIdx.x;
    const int half = NT * ND / 8;   // float4s per pass
    const float4* y4 = reinterpret_cast<const float4*>(g_y);
    #pragma unroll
    for (int u = 0; u < 2; ++u) {
        int i = base + u * half;
        int t = i >> 8, c = i & 255;
        float4 a = y4[(size_t)(2 * t) * 256 + c];
        float4 b = y4[(size_t)(2 * t + 1) * 256 + c];
        reinterpret_cast<float4*>(out)[i] =
            make_float4(a.x + b.x, a.y + b.y, a.z + b.z, a.w + b.w);
    }
}

extern "C" void kernel_launch(void* const* d_in, const int* in_sizes, int n_in,
                              void* d_out, int out_size) {
    const float* x     = (const float*)d_in[0];
    const float* wr    = (const float*)d_in[1];
    const float* w_in  = (const float*)d_in[2];
    const float* w_out = (const float*)d_in[3];
    float* out = (float*)d_out;

    float* logits;
    if (out_size >= NT * ND + NT * NE) {
        logits = out + (size_t)NT * ND;
    } else {
        cudaGetSymbolAddress((void**)&logits, g_logits_scratch);
    }

    __half *px16, *pwin16, *pwout16;
    cudaGetSymbolAddress((void**)&px16, g_x16);
    cudaGetSymbolAddress((void**)&pwin16, g_win16);
    cudaGetSymbolAddress((void**)&pwout16, g_wout16);

    prep_kernel<<<NT + CVT_BLOCKS, 256>>>(x, wr, logits, px16,
                                          w_in, pwin16, w_out, pwout16);
    ffn1_h<<<dim3(NH / 64, NT / 128, NE), 256>>>();
    ffn2_h<<<dim3(ND / 128, NT / 128, NE), 256>>>();
    combine_kernel<<<(NT * ND / 8 + 255) / 256, 256>>>(out);
}

// round 16
// speedup vs baseline: 1.5545x; 1.0014x over previous
#include <cuda_runtime.h>
#include <cuda_fp16.h>
#include <math.h>
#include <stdint.h>

#define NT 4096      // tokens = B*S
#define ND 1024      // hidden
#define NH 512       // intermediate
#define NE 8         // experts

// ---- device scratch (static; no allocations allowed) ----
__device__ int    g_cnt[NE];          // zero-init at load; re-zeroed by combine_kernel each call
__device__ int    g_tokslot[NE * NT];
__device__ float  g_gate[NE * NT];
__device__ __half g_x16[(size_t)NT * ND];
__device__ __half g_win16[(size_t)NE * 2 * NH * ND];
__device__ __half g_wout16[(size_t)NE * ND * NH];
__device__ __half g_h16[(size_t)NE * NT * NH];
__device__ float  g_y[(size_t)NT * 2 * ND];
__device__ float  g_logits_scratch[(size_t)NT * NE];

// ======================= helpers =======================
__device__ __forceinline__ uint32_t smem_u32(const void* p) {
    uint32_t a;
    asm("{ .reg .u64 t; cvta.to.shared.u64 t, %1; cvt.u32.u64 %0, t; }" : "=r"(a) : "l"(p));
    return a;
}
#define CPA16(dst, src) asm volatile("cp.async.cg.shared.global [%0], [%1], 16;" :: "r"(dst), "l"(src))
#define CPCOMMIT()      asm volatile("cp.async.commit_group;")
#define CPWAIT(n)       asm volatile("cp.async.wait_group %0;" :: "n"(n))
#define LDM_X4(r0, r1, r2, r3, addr) \
    asm volatile("ldmatrix.sync.aligned.m8n8.x4.shared.b16 {%0,%1,%2,%3}, [%4];" \
        : "=r"(r0), "=r"(r1), "=r"(r2), "=r"(r3) : "r"(addr))
#define MMA16(d, a, b0, b1) \
    asm volatile("mma.sync.aligned.m16n8k16.row.col.f32.f16.f16.f32 " \
        "{%0,%1,%2,%3}, {%4,%5,%6,%7}, {%8,%9}, {%0,%1,%2,%3};" \
        : "+f"((d)[0]), "+f"((d)[1]), "+f"((d)[2]), "+f"((d)[3]) \
        : "r"((a)[0]), "r"((a)[1]), "r"((a)[2]), "r"((a)[3]), "r"(b0), "r"(b1))

// =====================================================================
// prep_kernel: blocks [0, NT) = router (+x fp16 convert);
//              blocks [NT, NT + CVT_BLOCKS) = w_in fp32->fp16 convert.
// (w_out convert rides inside ffn1's grid where DRAM is idle.)
#define NWI (NE * 2 * NH * ND / 4)       // 2097152 float4
#define NWO (NE * ND * NH / 4)           // 1048576 float4
#define CVT_THREADS 524288
#define CVT_BLOCKS (CVT_THREADS / 256)   // 2048
__global__ void prep_kernel(const float* __restrict__ x,
                            const float* __restrict__ wr,
                            float* __restrict__ logits_out,
                            __half* __restrict__ x16,
                            const float* __restrict__ win, __half* __restrict__ dwin) {
    if (blockIdx.x < NT) {
        // ---- router + x convert ----
        int t = blockIdx.x;
        int w = threadIdx.x >> 5;
        int l = threadIdx.x & 31;
        const float* xr = x + (size_t)t * ND;
        const float* wrow = wr + w * ND;
        float s = 0.f;
        #pragma unroll 8
        for (int j = l; j < ND; j += 32) s += xr[j] * wrow[j];
        #pragma unroll
        for (int o = 16; o > 0; o >>= 1) s += __shfl_xor_sync(0xffffffffu, s, o);
        __shared__ float lg[NE];
        if (l == 0) { lg[w] = s; logits_out[(size_t)t * NE + w] = s; }

        {
            int j = threadIdx.x * 4;
            float4 v = *reinterpret_cast<const float4*>(xr + j);
            __half2* dst = reinterpret_cast<__half2*>(x16 + (size_t)t * ND + j);
            dst[0] = __floats2half2_rn(v.x, v.y);
            dst[1] = __floats2half2_rn(v.z, v.w);
        }

        __syncthreads();
        if (threadIdx.x == 0) {
            int i0 = 0; float v0 = lg[0];
            #pragma unroll
            for (int e = 1; e < NE; ++e) if (lg[e] > v0) { v0 = lg[e]; i0 = e; }
            int i1 = -1; float v1 = -INFINITY;
            #pragma unroll
            for (int e = 0; e < NE; ++e) if (e != i0 && lg[e] > v1) { v1 = lg[e]; i1 = e; }
            float e1 = expf(v1 - v0);
            float inv = 1.f / (1.f + e1);
            int p0 = atomicAdd(&g_cnt[i0], 1);
            g_tokslot[i0 * NT + p0] = t * 2;
            g_gate[i0 * NT + p0]    = inv;
            int p1 = atomicAdd(&g_cnt[i1], 1);
            g_tokslot[i1 * NT + p1] = t * 2 + 1;
            g_gate[i1 * NT + p1]    = e1 * inv;
        }
    } else {
        // ---- w_in convert: exactly 4 float4 per thread ----
        int tid = (blockIdx.x - NT) * blockDim.x + threadIdx.x;
        #pragma unroll
        for (int u = 0; u < 4; ++u) {
            int j = tid + u * CVT_THREADS;
            float4 v = reinterpret_cast<const float4*>(win)[j];
            reinterpret_cast<__half2*>(dwin)[2 * j]     = __floats2half2_rn(v.x, v.y);
            reinterpret_cast<__half2*>(dwin)[2 * j + 1] = __floats2half2_rn(v.z, v.w);
        }
    }
}

// Shared-mem geometry: row = 64B (32 halfs), chunk = 16B, swizzle c^=((row>>1)&3).
// Stage = A(128x32h, 8KB) + B(128x32h, 8KB) = 16KB; 3 stages = 48KB (static).
#define STAGE_BYTES 16384

// =====================================================================
// ffn1: C[128 x 128] = A(gathered x16 rows) @ B^T, fp16 mma, K = 1024.
// grid.x in [0,8)  : GEMM n-tiles (R12 config, unchanged).
// grid.x in [8,12) : w_out fp32->fp16 convert blocks (1024 blocks x 256 thr
//                    x 4 float4 = NWO), overlapped with the compute-bound
//                    GEMM blocks (DRAM was 95% idle). w_out16 is first read
//                    by ffn2, which launches after ffn1 completes.
// =====================================================================
__global__ void __launch_bounds__(256, 2)
ffn1_h(const float* __restrict__ wout, __half* __restrict__ dwout) {
    __shared__ __align__(128) uint8_t smem[3 * STAGE_BYTES];
    if (blockIdx.x >= 8) {
        int cid = (blockIdx.x - 8) + 4 * (blockIdx.y + 32 * blockIdx.z);  // 0..1023
        int tid = cid * 256 + threadIdx.x;                                // 0..262143
        #pragma unroll
        for (int u = 0; u < 4; ++u) {
            int j = tid + u * 262144;   // covers NWO = 1048576 float4
            float4 v = reinterpret_cast<const float4*>(wout)[j];
            reinterpret_cast<__half2*>(dwout)[2 * j]     = __floats2half2_rn(v.x, v.y);
            reinterpret_cast<__half2*>(dwout)[2 * j + 1] = __floats2half2_rn(v.z, v.w);
        }
        return;
    }
    int e = blockIdx.z;
    int cnt = g_cnt[e];
    int m0 = blockIdx.y * 128;
    if (m0 >= cnt) return;
    int n0 = blockIdx.x * 64;

    uint32_t sb = smem_u32(smem);
    int t = threadIdx.x;
    int lane = t & 31, wid = t >> 5;
    int wm = wid & 1, wn = wid >> 1;          // warp grid 2(M) x 4(N)
    int grp = lane >> 2, tig = lane & 3;
    int rA = (lane & 7) + ((lane >> 3) & 1) * 8;   // ldmatrix row-in-16
    int csel = lane >> 4;                          // ldmatrix chunk select

    int lr = t >> 2;             // 0..63
    int lc = t & 3;
    int r0 = m0 + lr, r1 = r0 + 64;
    int rc0 = r0 < cnt ? r0 : cnt - 1;
    int rc1 = r1 < cnt ? r1 : cnt - 1;
    const __half* asrc0 = g_x16 + (size_t)(g_tokslot[e * NT + rc0] >> 1) * ND + lc * 8;
    const __half* asrc1 = g_x16 + (size_t)(g_tokslot[e * NT + rc1] >> 1) * ND + lc * 8;
    // interleaved B-row mapping for tile rows nn0=lr, nn1=lr+64
    int nn0 = lr, nn1 = lr + 64;
    int j0 = nn0 & 31, j1 = nn1 & 31;
    int brow0 = (j0 < 16) ? (n0 + (nn0 >> 5) * 16 + j0) : (NH + n0 + (nn0 >> 5) * 16 + j0 - 16);
    int brow1 = (j1 < 16) ? (n0 + (nn1 >> 5) * 16 + j1) : (NH + n0 + (nn1 >> 5) * 16 + j1 - 16);
    const __half* bsrc0 = g_win16 + ((size_t)e * (2 * NH) + brow0) * ND + lc * 8;
    const __half* bsrc1 = g_win16 + ((size_t)e * (2 * NH) + brow1) * ND + lc * 8;
    uint32_t swc = (uint32_t)((lc ^ ((lr >> 1) & 3)) << 4);
    uint32_t dA0 = lr * 64 + swc;
    uint32_t dA1 = dA0 + 4096;

    uint32_t relA[4], relB0, relB1;
    #pragma unroll
    for (int mt = 0; mt < 4; ++mt) {
        int row = wm * 64 + mt * 16 + rA;
        relA[mt] = (uint32_t)(row * 64) + ((uint32_t)((((row >> 1) & 3) ^ csel)) << 4);
    }
    {
        int row = wn * 32 + rA;
        relB0 = 8192u + (uint32_t)(row * 64) + ((uint32_t)((((row >> 1) & 3) ^ csel)) << 4);
        row += 16;
        relB1 = 8192u + (uint32_t)(row * 64) + ((uint32_t)((((row >> 1) & 3) ^ csel)) << 4);
    }

    float acc[4][4][4];
    #pragma unroll
    for (int i = 0; i < 4; ++i)
        #pragma unroll
        for (int j = 0; j < 4; ++j)
            #pragma unroll
            for (int q = 0; q < 4; ++q) acc[i][j][q] = 0.f;

    #pragma unroll
    for (int s = 0; s < 2; ++s) {
        uint32_t st = sb + s * STAGE_BYTES;
        CPA16(st + dA0, asrc0 + s * 32);
        CPA16(st + dA1, asrc1 + s * 32);
        CPA16(st + 8192 + dA0, bsrc0 + s * 32);
        CPA16(st + 8192 + dA1, bsrc1 + s * 32);
        CPCOMMIT();
    }

    const int NK = ND / 32;   // 32
    int stage = 0;
    for (int kt = 0; kt < NK; ++kt) {
        if (kt < NK - 1) { CPWAIT(1); } else { CPWAIT(0); }
        __syncthreads();
        if (kt + 2 < NK) {
            uint32_t st = sb + ((kt + 2) % 3) * STAGE_BYTES;
            int off = (kt + 2) * 32;
            CPA16(st + dA0, asrc0 + off);
            CPA16(st + dA1, asrc1 + off);
            CPA16(st + 8192 + dA0, bsrc0 + off);
            CPA16(st + 8192 + dA1, bsrc1 + off);
            CPCOMMIT();
        }
        uint32_t As = sb + stage * STAGE_BYTES;
        uint32_t B0a[4], B1a[4], B0b[4], B1b[4];
        LDM_X4(B0a[0], B0a[1], B0a[2], B0a[3], As + relB0);
        LDM_X4(B1a[0], B1a[1], B1a[2], B1a[3], As + relB1);
        LDM_X4(B0b[0], B0b[1], B0b[2], B0b[3], As + (relB0 ^ 32u));
        LDM_X4(B1b[0], B1b[1], B1b[2], B1b[3], As + (relB1 ^ 32u));
        #pragma unroll
        for (int ks = 0; ks < 2; ++ks) {
            uint32_t kx = (uint32_t)(ks << 5);
            const uint32_t* B0 = ks ? B0b : B0a;
            const uint32_t* B1 = ks ? B1b : B1a;
            uint32_t a[4][4];
            #pragma unroll
            for (int mt = 0; mt < 4; ++mt)
                LDM_X4(a[mt][0], a[mt][1], a[mt][2], a[mt][3], As + (relA[mt] ^ kx));
            #pragma unroll
            for (int mt = 0; mt < 4; ++mt) {
                MMA16(acc[mt][0], a[mt], B0[0], B0[2]);
                MMA16(acc[mt][1], a[mt], B0[1], B0[3]);
                MMA16(acc[mt][2], a[mt], B1[0], B1[2]);
                MMA16(acc[mt][3], a[mt], B1[1], B1[3]);
            }
        }
        stage = stage + 1; if (stage == 3) stage = 0;
    }

    // epilogue: acc[mt][nt] (a-cols) pairs with acc[mt][nt+2] (b-cols), nt in {0,1}.
    #pragma unroll
    for (int mt = 0; mt < 4; ++mt) {
        #pragma unroll
        for (int hf = 0; hf < 2; ++hf) {
            int row = wm * 64 + mt * 16 + grp + hf * 8;
            int rr = m0 + row;
            if (rr < cnt) {
                __half* dst = g_h16 + ((size_t)e * NT + rr) * NH + n0 + wn * 16;
                #pragma unroll
                for (int nt = 0; nt < 2; ++nt) {
                    float a0 = acc[mt][nt][hf * 2 + 0];
                    float a1 = acc[mt][nt][hf * 2 + 1];
                    float b0 = acc[mt][nt + 2][hf * 2 + 0];
                    float b1 = acc[mt][nt + 2][hf * 2 + 1];
                    float h0 = a0 / (1.f + __expf(-a0)) * b0;
                    float h1 = a1 / (1.f + __expf(-a1)) * b1;
                    *(__half2*)(dst + nt * 8 + 2 * tig) = __floats2half2_rn(h0, h1);
                }
            }
        }
    }
}

// =====================================================================
// ffn2: C[128 x 128] = g_h16 rows @ w_out16 rows^T, K = 512.
// Epilogue: gate-scale, scatter rows to g_y[tokslot].
// =====================================================================
__global__ void __launch_bounds__(256, 2)
ffn2_h(void) {
    __shared__ __align__(128) uint8_t smem[3 * STAGE_BYTES];
    int e = blockIdx.z;
    int cnt = g_cnt[e];
    int m0 = blockIdx.y * 128;
    if (m0 >= cnt) return;
    int n0 = blockIdx.x * 128;

    uint32_t sb = smem_u32(smem);
    int t = threadIdx.x;
    int lane = t & 31, wid = t >> 5;
    int wm = wid & 1, wn = wid >> 1;
    int grp = lane >> 2, tig = lane & 3;
    int rA = (lane & 7) + ((lane >> 3) & 1) * 8;
    int csel = lane >> 4;

    int lr = t >> 2;
    int lc = t & 3;
    int r0 = m0 + lr, r1 = r0 + 64;
    int rc0 = r0 < cnt ? r0 : cnt - 1;
    int rc1 = r1 < cnt ? r1 : cnt - 1;
    const __half* asrc0 = g_h16 + ((size_t)e * NT + rc0) * NH + lc * 8;
    const __half* asrc1 = g_h16 + ((size_t)e * NT + rc1) * NH + lc * 8;
    const __half* bsrc0 = g_wout16 + ((size_t)e * ND + n0 + lr) * NH + lc * 8;
    const __half* bsrc1 = g_wout16 + ((size_t)e * ND + n0 + lr + 64) * NH + lc * 8;
    uint32_t swc = (uint32_t)((lc ^ ((lr >> 1) & 3)) << 4);
    uint32_t dA0 = lr * 64 + swc;
    uint32_t dA1 = dA0 + 4096;

    uint32_t relA[4], relB0, relB1;
    #pragma unroll
    for (int mt = 0; mt < 4; ++mt) {
        int row = wm * 64 + mt * 16 + rA;
        relA[mt] = (uint32_t)(row * 64) + ((uint32_t)((((row >> 1) & 3) ^ csel)) << 4);
    }
    {
        int row = wn * 32 + rA;
        relB0 = 8192u + (uint32_t)(row * 64) + ((uint32_t)((((row >> 1) & 3) ^ csel)) << 4);
        row += 16;
        relB1 = 8192u + (uint32_t)(row * 64) + ((uint32_t)((((row >> 1) & 3) ^ csel)) << 4);
    }

    float acc[4][4][4];
    #pragma unroll
    for (int i = 0; i < 4; ++i)
        #pragma unroll
        for (int j = 0; j < 4; ++j)
            #pragma unroll
            for (int q = 0; q < 4; ++q) acc[i][j][q] = 0.f;

    #pragma unroll
    for (int s = 0; s < 2; ++s) {
        uint32_t st = sb + s * STAGE_BYTES;
        CPA16(st + dA0, asrc0 + s * 32);
        CPA16(st + dA1, asrc1 + s * 32);
        CPA16(st + 8192 + dA0, bsrc0 + s * 32);
        CPA16(st + 8192 + dA1, bsrc1 + s * 32);
        CPCOMMIT();
    }

    const int NK = NH / 32;   // 16
    int stage = 0;
    for (int kt = 0; kt < NK; ++kt) {
        if (kt < NK - 1) { CPWAIT(1); } else { CPWAIT(0); }
        __syncthreads();
        if (kt + 2 < NK) {
            uint32_t st = sb + ((kt + 2) % 3) * STAGE_BYTES;
            int off = (kt + 2) * 32;
            CPA16(st + dA0, asrc0 + off);
            CPA16(st + dA1, asrc1 + off);
            CPA16(st + 8192 + dA0, bsrc0 + off);
            CPA16(st + 8192 + dA1, bsrc1 + off);
            CPCOMMIT();
        }
        uint32_t As = sb + stage * STAGE_BYTES;
        uint32_t B0a[4], B1a[4], B0b[4], B1b[4];
        LDM_X4(B0a[0], B0a[1], B0a[2], B0a[3], As + relB0);
        LDM_X4(B1a[0], B1a[1], B1a[2], B1a[3], As + relB1);
        LDM_X4(B0b[0], B0b[1], B0b[2], B0b[3], As + (relB0 ^ 32u));
        LDM_X4(B1b[0], B1b[1], B1b[2], B1b[3], As + (relB1 ^ 32u));
        #pragma unroll
        for (int ks = 0; ks < 2; ++ks) {
            uint32_t kx = (uint32_t)(ks << 5);
            const uint32_t* B0 = ks ? B0b : B0a;
            const uint32_t* B1 = ks ? B1b : B1a;
            uint32_t a[4][4];
            #pragma unroll
            for (int mt = 0; mt < 4; ++mt)
                LDM_X4(a[mt][0], a[mt][1], a[mt][2], a[mt][3], As + (relA[mt] ^ kx));
            #pragma unroll
            for (int mt = 0; mt < 4; ++mt) {
                MMA16(acc[mt][0], a[mt], B0[0], B0[2]);
                MMA16(acc[mt][1], a[mt], B0[1], B0[3]);
                MMA16(acc[mt][2], a[mt], B1[0], B1[2]);
                MMA16(acc[mt][3], a[mt], B1[1], B1[3]);
            }
        }
        stage = stage + 1; if (stage == 3) stage = 0;
    }

    #pragma unroll
    for (int mt = 0; mt < 4; ++mt) {
        #pragma unroll
        for (int hf = 0; hf < 2; ++hf) {
            int row = wm * 64 + mt * 16 + grp + hf * 8;
            int rr = m0 + row;
            if (rr < cnt) {
                int   ts = g_tokslot[e * NT + rr];
                float gt = g_gate[e * NT + rr];
                float* dst = g_y + (size_t)ts * ND + n0;
                #pragma unroll
                for (int nt = 0; nt < 4; ++nt) {
                    int col = wn * 32 + nt * 8 + 2 * tig;
                    float2 v = make_float2(acc[mt][nt][hf * 2 + 0] * gt,
                                           acc[mt][nt][hf * 2 + 1] * gt);
                    *(float2*)(dst + col) = v;
                }
            }
        }
    }
}

// out[t] = y[2t] + y[2t+1]; 2 float4 per thread (MLP=2).
// Also re-zeroes g_cnt for the next graph replay.
__global__ void combine_kernel(float* __restrict__ out) {
    if (blockIdx.x == 0 && threadIdx.x < NE) g_cnt[threadIdx.x] = 0;
    int base = blockIdx.x * blockDim.x + threadIdx.x;
    const int half = NT * ND / 8;   // float4s per pass
    const float4* y4 = reinterpret_cast<const float4*>(g_y);
    #pragma unroll
    for (int u = 0; u < 2; ++u) {
        int i = base + u * half;
        int t = i >> 8, c = i & 255;
        float4 a = y4[(size_t)(2 * t) * 256 + c];
        float4 b = y4[(size_t)(2 * t + 1) * 256 + c];
        reinterpret_cast<float4*>(out)[i] =
            make_float4(a.x + b.x, a.y + b.y, a.z + b.z, a.w + b.w);
    }
}

extern "C" void kernel_launch(void* const* d_in, const int* in_sizes, int n_in,
                              void* d_out, int out_size) {
    const float* x     = (const float*)d_in[0];
    const float* wr    = (const float*)d_in[1];
    const float* w_in  = (const float*)d_in[2];
    const float* w_out = (const float*)d_in[3];
    float* out = (float*)d_out;

    float* logits;
    if (out_size >= NT * ND + NT * NE) {
        logits = out + (size_t)NT * ND;
    } else {
        cudaGetSymbolAddress((void**)&logits, g_logits_scratch);
    }

    __half *px16, *pwin16, *pwout16;
    cudaGetSymbolAddress((void**)&px16, g_x16);
    cudaGetSymbolAddress((void**)&pwin16, g_win16);
    cudaGetSymbolAddress((void**)&pwout16, g_wout16);

    prep_kernel<<<NT + CVT_BLOCKS, 256>>>(x, wr, logits, px16, w_in, pwin16);
    ffn1_h<<<dim3(12, NT / 128, NE), 256>>>(w_out, pwout16);
    ffn2_h<<<dim3(ND / 128, NT / 128, NE), 256>>>();
    combine_kernel<<<(NT * ND / 8 + 255) / 256, 256>>>(out);
}

// round 17
// speedup vs baseline: 1.6234x; 1.0443x over previous
#include <cuda_runtime.h>
#include <cuda_fp16.h>
#include <math.h>
#include <stdint.h>

#define NT 4096      // tokens = B*S
#define ND 1024      // hidden
#define NH 512       // intermediate
#define NE 8         // experts

// ---- device scratch (static; no allocations allowed) ----
__device__ int    g_cnt[NE];          // zero-init at load; re-zeroed by combine_kernel each call
__device__ int    g_tokslot[NE * NT];
__device__ float  g_gate[NE * NT];
__device__ __half g_x16[(size_t)NT * ND];
__device__ __half g_win16[(size_t)NE * 2 * NH * ND];
__device__ __half g_wout16[(size_t)NE * ND * NH];
__device__ __half g_h16[(size_t)NE * NT * NH];
__device__ float  g_y[(size_t)NT * 2 * ND];
__device__ float  g_logits_scratch[(size_t)NT * NE];

// ======================= helpers =======================
__device__ __forceinline__ uint32_t smem_u32(const void* p) {
    uint32_t a;
    asm("{ .reg .u64 t; cvta.to.shared.u64 t, %1; cvt.u32.u64 %0, t; }" : "=r"(a) : "l"(p));
    return a;
}
#define CPA16(dst, src) asm volatile("cp.async.cg.shared.global [%0], [%1], 16;" :: "r"(dst), "l"(src))
#define CPCOMMIT()      asm volatile("cp.async.commit_group;")
#define CPWAIT(n)       asm volatile("cp.async.wait_group %0;" :: "n"(n))
#define LDM_X4(r0, r1, r2, r3, addr) \
    asm volatile("ldmatrix.sync.aligned.m8n8.x4.shared.b16 {%0,%1,%2,%3}, [%4];" \
        : "=r"(r0), "=r"(r1), "=r"(r2), "=r"(r3) : "r"(addr))
#define MMA16(d, a, b0, b1) \
    asm volatile("mma.sync.aligned.m16n8k16.row.col.f32.f16.f16.f32 " \
        "{%0,%1,%2,%3}, {%4,%5,%6,%7}, {%8,%9}, {%0,%1,%2,%3};" \
        : "+f"((d)[0]), "+f"((d)[1]), "+f"((d)[2]), "+f"((d)[3]) \
        : "r"((a)[0]), "r"((a)[1]), "r"((a)[2]), "r"((a)[3]), "r"(b0), "r"(b1))

// =====================================================================
// prep_kernel: blocks [0, RT_BLOCKS) = batched router (8 tokens/block,
//              x staged in smem, wr row held in registers per warp);
//              blocks [RT_BLOCKS, RT_BLOCKS + CVT_BLOCKS) = w_in cvt.
#define NWI (NE * 2 * NH * ND / 4)       // 2097152 float4
#define CVT_THREADS 524288
#define CVT_BLOCKS (CVT_THREADS / 256)   // 2048
#define TPB 8                            // tokens per router block
#define RT_BLOCKS (NT / TPB)             // 512
__global__ void prep_kernel(const float* __restrict__ x,
                            const float* __restrict__ wr,
                            float* __restrict__ logits_out,
                            __half* __restrict__ x16,
                            const float* __restrict__ win, __half* __restrict__ dwin) {
    __shared__ float xs[TPB * ND];       // 32KB
    __shared__ float lg[TPB][NE];
    if (blockIdx.x < RT_BLOCKS) {
        int t0 = blockIdx.x * TPB;
        int w = threadIdx.x >> 5;        // warp = expert
        int l = threadIdx.x & 31;

        // stage 8 contiguous x rows into smem; convert to fp16 on the way
        {
            const float4* src = reinterpret_cast<const float4*>(x + (size_t)t0 * ND);
            float4* dst4 = reinterpret_cast<float4*>(xs);
            __half2* dst16 = reinterpret_cast<__half2*>(x16 + (size_t)t0 * ND);
            #pragma unroll
            for (int u = 0; u < TPB; ++u) {
                int idx = threadIdx.x + u * 256;          // 2048 float4 total
                float4 v = src[idx];
                dst4[idx] = v;
                dst16[2 * idx]     = __floats2half2_rn(v.x, v.y);
                dst16[2 * idx + 1] = __floats2half2_rn(v.z, v.w);
            }
        }

        // each warp loads its expert row into registers (j = l + 32k, ascending)
        float wrk[32];
        const float* wrow = wr + w * ND;
        #pragma unroll
        for (int k = 0; k < 32; ++k) wrk[k] = wrow[l + 32 * k];
        __syncthreads();

        // 8 dot products per warp; summation order identical to the
        // original per-token router (j ascending by lane stride 32).
        #pragma unroll
        for (int i = 0; i < TPB; ++i) {
            const float* xr = xs + i * ND;
            float s = 0.f;
            #pragma unroll 8
            for (int k = 0; k < 32; ++k) s += xr[l + 32 * k] * wrk[k];
            #pragma unroll
            for (int o = 16; o > 0; o >>= 1) s += __shfl_xor_sync(0xffffffffu, s, o);
            if (l == 0) {
                lg[i][w] = s;
                logits_out[(size_t)(t0 + i) * NE + w] = s;
            }
        }
        __syncthreads();

        // threads 0..7: top-2 + softmax + dispatch for one token each
        if (threadIdx.x < TPB) {
            int i = threadIdx.x;
            int t = t0 + i;
            int i0 = 0; float v0 = lg[i][0];
            #pragma unroll
            for (int e = 1; e < NE; ++e) if (lg[i][e] > v0) { v0 = lg[i][e]; i0 = e; }
            int i1 = -1; float v1 = -INFINITY;
            #pragma unroll
            for (int e = 0; e < NE; ++e) if (e != i0 && lg[i][e] > v1) { v1 = lg[i][e]; i1 = e; }
            float e1 = expf(v1 - v0);
            float inv = 1.f / (1.f + e1);
            int p0 = atomicAdd(&g_cnt[i0], 1);
            g_tokslot[i0 * NT + p0] = t * 2;
            g_gate[i0 * NT + p0]    = inv;
            int p1 = atomicAdd(&g_cnt[i1], 1);
            g_tokslot[i1 * NT + p1] = t * 2 + 1;
            g_gate[i1 * NT + p1]    = e1 * inv;
        }
    } else {
        // ---- w_in convert: exactly 4 float4 per thread ----
        int tid = (blockIdx.x - RT_BLOCKS) * blockDim.x + threadIdx.x;
        #pragma unroll
        for (int u = 0; u < 4; ++u) {
            int j = tid + u * CVT_THREADS;
            float4 v = reinterpret_cast<const float4*>(win)[j];
            reinterpret_cast<__half2*>(dwin)[2 * j]     = __floats2half2_rn(v.x, v.y);
            reinterpret_cast<__half2*>(dwin)[2 * j + 1] = __floats2half2_rn(v.z, v.w);
        }
    }
}

// Shared-mem geometry: row = 64B (32 halfs), chunk = 16B, swizzle c^=((row>>1)&3).
// Stage = A(128x32h, 8KB) + B(128x32h, 8KB) = 16KB; 3 stages = 48KB (static).
#define STAGE_BYTES 16384

// =====================================================================
// ffn1: C[128 x 128] = A(gathered x16 rows) @ B^T, fp16 mma, K = 1024.
// grid.x in [0,8)  : GEMM n-tiles. grid.x in [8,12): w_out fp32->fp16 cvt
// (overlapped with compute-bound GEMM blocks; w_out16 first read by ffn2).
// =====================================================================
__global__ void __launch_bounds__(256, 2)
ffn1_h(const float* __restrict__ wout, __half* __restrict__ dwout) {
    __shared__ __align__(128) uint8_t smem[3 * STAGE_BYTES];
    if (blockIdx.x >= 8) {
        int cid = (blockIdx.x - 8) + 4 * (blockIdx.y + 32 * blockIdx.z);  // 0..1023
        int tid = cid * 256 + threadIdx.x;
        #pragma unroll
        for (int u = 0; u < 4; ++u) {
            int j = tid + u * 262144;   // covers NWO = 1048576 float4
            float4 v = reinterpret_cast<const float4*>(wout)[j];
            reinterpret_cast<__half2*>(dwout)[2 * j]     = __floats2half2_rn(v.x, v.y);
            reinterpret_cast<__half2*>(dwout)[2 * j + 1] = __floats2half2_rn(v.z, v.w);
        }
        return;
    }
    int e = blockIdx.z;
    int cnt = g_cnt[e];
    int m0 = blockIdx.y * 128;
    if (m0 >= cnt) return;
    int n0 = blockIdx.x * 64;

    uint32_t sb = smem_u32(smem);
    int t = threadIdx.x;
    int lane = t & 31, wid = t >> 5;
    int wm = wid & 1, wn = wid >> 1;          // warp grid 2(M) x 4(N)
    int grp = lane >> 2, tig = lane & 3;
    int rA = (lane & 7) + ((lane >> 3) & 1) * 8;   // ldmatrix row-in-16
    int csel = lane >> 4;                          // ldmatrix chunk select

    int lr = t >> 2;             // 0..63
    int lc = t & 3;
    int r0 = m0 + lr, r1 = r0 + 64;
    int rc0 = r0 < cnt ? r0 : cnt - 1;
    int rc1 = r1 < cnt ? r1 : cnt - 1;
    const __half* asrc0 = g_x16 + (size_t)(g_tokslot[e * NT + rc0] >> 1) * ND + lc * 8;
    const __half* asrc1 = g_x16 + (size_t)(g_tokslot[e * NT + rc1] >> 1) * ND + lc * 8;
    // interleaved B-row mapping for tile rows nn0=lr, nn1=lr+64
    int nn0 = lr, nn1 = lr + 64;
    int j0 = nn0 & 31, j1 = nn1 & 31;
    int brow0 = (j0 < 16) ? (n0 + (nn0 >> 5) * 16 + j0) : (NH + n0 + (nn0 >> 5) * 16 + j0 - 16);
    int brow1 = (j1 < 16) ? (n0 + (nn1 >> 5) * 16 + j1) : (NH + n0 + (nn1 >> 5) * 16 + j1 - 16);
    const __half* bsrc0 = g_win16 + ((size_t)e * (2 * NH) + brow0) * ND + lc * 8;
    const __half* bsrc1 = g_win16 + ((size_t)e * (2 * NH) + brow1) * ND + lc * 8;
    uint32_t swc = (uint32_t)((lc ^ ((lr >> 1) & 3)) << 4);
    uint32_t dA0 = lr * 64 + swc;
    uint32_t dA1 = dA0 + 4096;

    uint32_t relA[4], relB0, relB1;
    #pragma unroll
    for (int mt = 0; mt < 4; ++mt) {
        int row = wm * 64 + mt * 16 + rA;
        relA[mt] = (uint32_t)(row * 64) + ((uint32_t)((((row >> 1) & 3) ^ csel)) << 4);
    }
    {
        int row = wn * 32 + rA;
        relB0 = 8192u + (uint32_t)(row * 64) + ((uint32_t)((((row >> 1) & 3) ^ csel)) << 4);
        row += 16;
        relB1 = 8192u + (uint32_t)(row * 64) + ((uint32_t)((((row >> 1) & 3) ^ csel)) << 4);
    }

    float acc[4][4][4];
    #pragma unroll
    for (int i = 0; i < 4; ++i)
        #pragma unroll
        for (int j = 0; j < 4; ++j)
            #pragma unroll
            for (int q = 0; q < 4; ++q) acc[i][j][q] = 0.f;

    #pragma unroll
    for (int s = 0; s < 2; ++s) {
        uint32_t st = sb + s * STAGE_BYTES;
        CPA16(st + dA0, asrc0 + s * 32);
        CPA16(st + dA1, asrc1 + s * 32);
        CPA16(st + 8192 + dA0, bsrc0 + s * 32);
        CPA16(st + 8192 + dA1, bsrc1 + s * 32);
        CPCOMMIT();
    }

    const int NK = ND / 32;   // 32
    int stage = 0;
    for (int kt = 0; kt < NK; ++kt) {
        if (kt < NK - 1) { CPWAIT(1); } else { CPWAIT(0); }
        __syncthreads();
        if (kt + 2 < NK) {
            uint32_t st = sb + ((kt + 2) % 3) * STAGE_BYTES;
            int off = (kt + 2) * 32;
            CPA16(st + dA0, asrc0 + off);
            CPA16(st + dA1, asrc1 + off);
            CPA16(st + 8192 + dA0, bsrc0 + off);
            CPA16(st + 8192 + dA1, bsrc1 + off);
            CPCOMMIT();
        }
        uint32_t As = sb + stage * STAGE_BYTES;
        uint32_t B0a[4], B1a[4], B0b[4], B1b[4];
        LDM_X4(B0a[0], B0a[1], B0a[2], B0a[3], As + relB0);
        LDM_X4(B1a[0], B1a[1], B1a[2], B1a[3], As + relB1);
        LDM_X4(B0b[0], B0b[1], B0b[2], B0b[3], As + (relB0 ^ 32u));
        LDM_X4(B1b[0], B1b[1], B1b[2], B1b[3], As + (relB1 ^ 32u));
        #pragma unroll
        for (int ks = 0; ks < 2; ++ks) {
            uint32_t kx = (uint32_t)(ks << 5);
            const uint32_t* B0 = ks ? B0b : B0a;
            const uint32_t* B1 = ks ? B1b : B1a;
            uint32_t a[4][4];
            #pragma unroll
            for (int mt = 0; mt < 4; ++mt)
                LDM_X4(a[mt][0], a[mt][1], a[mt][2], a[mt][3], As + (relA[mt] ^ kx));
            #pragma unroll
            for (int mt = 0; mt < 4; ++mt) {
                MMA16(acc[mt][0], a[mt], B0[0], B0[2]);
                MMA16(acc[mt][1], a[mt], B0[1], B0[3]);
                MMA16(acc[mt][2], a[mt], B1[0], B1[2]);
                MMA16(acc[mt][3], a[mt], B1[1], B1[3]);
            }
        }
        stage = stage + 1; if (stage == 3) stage = 0;
    }

    // epilogue: acc[mt][nt] (a-cols) pairs with acc[mt][nt+2] (b-cols), nt in {0,1}.
    #pragma unroll
    for (int mt = 0; mt < 4; ++mt) {
        #pragma unroll
        for (int hf = 0; hf < 2; ++hf) {
            int row = wm * 64 + mt * 16 + grp + hf * 8;
            int rr = m0 + row;
            if (rr < cnt) {
                __half* dst = g_h16 + ((size_t)e * NT + rr) * NH + n0 + wn * 16;
                #pragma unroll
                for (int nt = 0; nt < 2; ++nt) {
                    float a0 = acc[mt][nt][hf * 2 + 0];
                    float a1 = acc[mt][nt][hf * 2 + 1];
                    float b0 = acc[mt][nt + 2][hf * 2 + 0];
                    float b1 = acc[mt][nt + 2][hf * 2 + 1];
                    float h0 = a0 / (1.f + __expf(-a0)) * b0;
                    float h1 = a1 / (1.f + __expf(-a1)) * b1;
                    *(__half2*)(dst + nt * 8 + 2 * tig) = __floats2half2_rn(h0, h1);
                }
            }
        }
    }
}

// =====================================================================
// ffn2: C[128 x 128] = g_h16 rows @ w_out16 rows^T, K = 512.
// Epilogue: gate-scale, scatter rows to g_y[tokslot].
// =====================================================================
__global__ void __launch_bounds__(256, 2)
ffn2_h(void) {
    __shared__ __align__(128) uint8_t smem[3 * STAGE_BYTES];
    int e = blockIdx.z;
    int cnt = g_cnt[e];
    int m0 = blockIdx.y * 128;
    if (m0 >= cnt) return;
    int n0 = blockIdx.x * 128;

    uint32_t sb = smem_u32(smem);
    int t = threadIdx.x;
    int lane = t & 31, wid = t >> 5;
    int wm = wid & 1, wn = wid >> 1;
    int grp = lane >> 2, tig = lane & 3;
    int rA = (lane & 7) + ((lane >> 3) & 1) * 8;
    int csel = lane >> 4;

    int lr = t >> 2;
    int lc = t & 3;
    int r0 = m0 + lr, r1 = r0 + 64;
    int rc0 = r0 < cnt ? r0 : cnt - 1;
    int rc1 = r1 < cnt ? r1 : cnt - 1;
    const __half* asrc0 = g_h16 + ((size_t)e * NT + rc0) * NH + lc * 8;
    const __half* asrc1 = g_h16 + ((size_t)e * NT + rc1) * NH + lc * 8;
    const __half* bsrc0 = g_wout16 + ((size_t)e * ND + n0 + lr) * NH + lc * 8;
    const __half* bsrc1 = g_wout16 + ((size_t)e * ND + n0 + lr + 64) * NH + lc * 8;
    uint32_t swc = (uint32_t)((lc ^ ((lr >> 1) & 3)) << 4);
    uint32_t dA0 = lr * 64 + swc;
    uint32_t dA1 = dA0 + 4096;

    uint32_t relA[4], relB0, relB1;
    #pragma unroll
    for (int mt = 0; mt < 4; ++mt) {
        int row = wm * 64 + mt * 16 + rA;
        relA[mt] = (uint32_t)(row * 64) + ((uint32_t)((((row >> 1) & 3) ^ csel)) << 4);
    }
    {
        int row = wn * 32 + rA;
        relB0 = 8192u + (uint32_t)(row * 64) + ((uint32_t)((((row >> 1) & 3) ^ csel)) << 4);
        row += 16;
        relB1 = 8192u + (uint32_t)(row * 64) + ((uint32_t)((((row >> 1) & 3) ^ csel)) << 4);
    }

    float acc[4][4][4];
    #pragma unroll
    for (int i = 0; i < 4; ++i)
        #pragma unroll
        for (int j = 0; j < 4; ++j)
            #pragma unroll
            for (int q = 0; q < 4; ++q) acc[i][j][q] = 0.f;

    #pragma unroll
    for (int s = 0; s < 2; ++s) {
        uint32_t st = sb + s * STAGE_BYTES;
        CPA16(st + dA0, asrc0 + s * 32);
        CPA16(st + dA1, asrc1 + s * 32);
        CPA16(st + 8192 + dA0, bsrc0 + s * 32);
        CPA16(st + 8192 + dA1, bsrc1 + s * 32);
        CPCOMMIT();
    }

    const int NK = NH / 32;   // 16
    int stage = 0;
    for (int kt = 0; kt < NK; ++kt) {
        if (kt < NK - 1) { CPWAIT(1); } else { CPWAIT(0); }
        __syncthreads();
        if (kt + 2 < NK) {
            uint32_t st = sb + ((kt + 2) % 3) * STAGE_BYTES;
            int off = (kt + 2) * 32;
            CPA16(st + dA0, asrc0 + off);
            CPA16(st + dA1, asrc1 + off);
            CPA16(st + 8192 + dA0, bsrc0 + off);
            CPA16(st + 8192 + dA1, bsrc1 + off);
            CPCOMMIT();
        }
        uint32_t As = sb + stage * STAGE_BYTES;
        uint32_t B0a[4], B1a[4], B0b[4], B1b[4];
        LDM_X4(B0a[0], B0a[1], B0a[2], B0a[3], As + relB0);
        LDM_X4(B1a[0], B1a[1], B1a[2], B1a[3], As + relB1);
        LDM_X4(B0b[0], B0b[1], B0b[2], B0b[3], As + (relB0 ^ 32u));
        LDM_X4(B1b[0], B1b[1], B1b[2], B1b[3], As + (relB1 ^ 32u));
        #pragma unroll
        for (int ks = 0; ks < 2; ++ks) {
            uint32_t kx = (uint32_t)(ks << 5);
            const uint32_t* B0 = ks ? B0b : B0a;
            const uint32_t* B1 = ks ? B1b : B1a;
            uint32_t a[4][4];
            #pragma unroll
            for (int mt = 0; mt < 4; ++mt)
                LDM_X4(a[mt][0], a[mt][1], a[mt][2], a[mt][3], As + (relA[mt] ^ kx));
            #pragma unroll
            for (int mt = 0; mt < 4; ++mt) {
                MMA16(acc[mt][0], a[mt], B0[0], B0[2]);
                MMA16(acc[mt][1], a[mt], B0[1], B0[3]);
                MMA16(acc[mt][2], a[mt], B1[0], B1[2]);
                MMA16(acc[mt][3], a[mt], B1[1], B1[3]);
            }
        }
        stage = stage + 1; if (stage == 3) stage = 0;
    }

    #pragma unroll
    for (int mt = 0; mt < 4; ++mt) {
        #pragma unroll
        for (int hf = 0; hf < 2; ++hf) {
            int row = wm * 64 + mt * 16 + grp + hf * 8;
            int rr = m0 + row;
            if (rr < cnt) {
                int   ts = g_tokslot[e * NT + rr];
                float gt = g_gate[e * NT + rr];
                float* dst = g_y + (size_t)ts * ND + n0;
                #pragma unroll
                for (int nt = 0; nt < 4; ++nt) {
                    int col = wn * 32 + nt * 8 + 2 * tig;
                    float2 v = make_float2(acc[mt][nt][hf * 2 + 0] * gt,
                                           acc[mt][nt][hf * 2 + 1] * gt);
                    *(float2*)(dst + col) = v;
                }
            }
        }
    }
}

// out[t] = y[2t] + y[2t+1]; 2 float4 per thread (MLP=2).
// Also re-zeroes g_cnt for the next graph replay.
__global__ void combine_kernel(float* __restrict__ out) {
    if (blockIdx.x == 0 && threadIdx.x < NE) g_cnt[threadIdx.x] = 0;
    int base = blockIdx.x * blockDim.x + threadIdx.x;
    const int half = NT * ND / 8;   // float4s per pass
    const float4* y4 = reinterpret_cast<const float4*>(g_y);
    #pragma unroll
    for (int u = 0; u < 2; ++u) {
        int i = base + u * half;
        int t = i >> 8, c = i & 255;
        float4 a = y4[(size_t)(2 * t) * 256 + c];
        float4 b = y4[(size_t)(2 * t + 1) * 256 + c];
        reinterpret_cast<float4*>(out)[i] =
            make_float4(a.x + b.x, a.y + b.y, a.z + b.z, a.w + b.w);
    }
}

extern "C" void kernel_launch(void* const* d_in, const int* in_sizes, int n_in,
                              void* d_out, int out_size) {
    const float* x     = (const float*)d_in[0];
    const float* wr    = (const float*)d_in[1];
    const float* w_in  = (const float*)d_in[2];
    const float* w_out = (const float*)d_in[3];
    float* out = (float*)d_out;

    float* logits;
    if (out_size >= NT * ND + NT * NE) {
        logits = out + (size_t)NT * ND;
    } else {
        cudaGetSymbolAddress((void**)&logits, g_logits_scratch);
    }

    __half *px16, *pwin16, *pwout16;
    cudaGetSymbolAddress((void**)&px16, g_x16);
    cudaGetSymbolAddress((void**)&pwin16, g_win16);
    cudaGetSymbolAddress((void**)&pwout16, g_wout16);

    prep_kernel<<<RT_BLOCKS + CVT_BLOCKS, 256>>>(x, wr, logits, px16, w_in, pwin16);
    ffn1_h<<<dim3(12, NT / 128, NE), 256>>>(w_out, pwout16);
    ffn2_h<<<dim3(ND / 128, NT / 128, NE), 256>>>();
    combine_kernel<<<(NT * ND / 8 + 255) / 256, 256>>>(out);
}